// round 12
// baseline (speedup 1.0000x reference)
#include <cuda_runtime.h>
#include <cuda_bf16.h>
#include <stdint.h>

#define NN 32000
#define NE 512000

// ---------------- persistent device scratch ----------------
__device__ float g_node[NN * 32];
__device__ float g_edge[NE * 32];
__device__ float g_agg [NN * 32];
__device__ __align__(16) unsigned char g_whi[786432];
__device__ __align__(16) unsigned char g_wlo[786432];

// smem byte offsets (64-row tiles)
#define A_HI 0               // 64 x 272
#define A_LO 17408
#define B_HI 34816           // up to 128 n-rows x 272
#define B_LO 69632
#define S_OUT 104448         // DEC row-reduce buffer (64 floats)
#define S_W0  104960         // 384 floats
#define SM_DYN 106496
#define ASTR 272             // row stride bytes (136 bf16 / 68 words)

__device__ __forceinline__ uint32_t smem_u32(const void* p) {
    uint32_t a;
    asm("{ .reg .u64 t; cvta.to.shared.u64 t, %1; cvt.u32.u64 %0, t; }" : "=r"(a) : "l"(p));
    return a;
}

#define LDSM4(d, addr) \
    asm volatile("ldmatrix.sync.aligned.m8n8.x4.shared.b16 {%0,%1,%2,%3}, [%4];" \
        : "=r"((d)[0]), "=r"((d)[1]), "=r"((d)[2]), "=r"((d)[3]) : "r"(addr))

#define MMA816(c, a, b0, b1) \
    asm volatile("mma.sync.aligned.m16n8k16.row.col.f32.bf16.bf16.f32 " \
        "{%0,%1,%2,%3}, {%4,%5,%6,%7}, {%8,%9}, {%0,%1,%2,%3};" \
        : "+f"((c)[0]), "+f"((c)[1]), "+f"((c)[2]), "+f"((c)[3]) \
        : "r"((a)[0]), "r"((a)[1]), "r"((a)[2]), "r"((a)[3]), "r"(b0), "r"(b1))

#define CP16(dst, src) \
    asm volatile("cp.async.cg.shared.global [%0], [%1], 16;" :: "r"(dst), "l"(src))
#define CP_COMMIT() asm volatile("cp.async.commit_group;" ::: "memory")
#define CP_WAIT0()  asm volatile("cp.async.wait_group 0;" ::: "memory")

#define REDV2(ptr, v0, v1) \
    asm volatile("red.global.add.v2.f32 [%0], {%1,%2};" :: "l"(ptr), "f"(v0), "f"(v1) : "memory")

// pack two bf16: lower k index in lower 16 bits
__device__ __forceinline__ uint32_t packbf(float e_lo, float e_hi) {
    return (uint32_t)__bfloat16_as_ushort(__float2bfloat16(e_lo))
         | ((uint32_t)__bfloat16_as_ushort(__float2bfloat16(e_hi)) << 16);
}
__device__ __forceinline__ void split_pair(float v0, float v1, uint32_t& hi, uint32_t& lo) {
    float h0 = __bfloat162float(__float2bfloat16(v0));
    float h1 = __bfloat162float(__float2bfloat16(v1));
    hi = packbf(v0, v1);
    lo = packbf(v0 - h0, v1 - h1);
}
__device__ __forceinline__ void storeA4(char* sm, int row, int k, float x, float y, float z, float w) {
    uint32_t h0, l0, h1, l1;
    split_pair(x, y, h0, l0);
    split_pair(z, w, h1, l1);
    *(uint2*)(sm + A_HI + row * ASTR + k * 2) = make_uint2(h0, h1);
    *(uint2*)(sm + A_LO + row * ASTR + k * 2) = make_uint2(l0, l1);
}

// async copy of pre-split weight tiles into B_HI/B_LO
__device__ __forceinline__ void loadB_async(uint32_t smb, int wd, int cnt16, int tid) {
    const char* gH = (const char*)g_whi + wd;
    const char* gL = (const char*)g_wlo + wd;
    uint32_t dH = smb + B_HI, dL = smb + B_LO;
    for (int i = tid; i < cnt16; i += 256) {
        CP16(dH + i * 16, gH + (size_t)i * 16);
        CP16(dL + i * 16, gL + (size_t)i * 16);
    }
}

// ---------------- GEMM: warp tile (MT*16 rows) x (NT8*8 cols), bf16 split, fp32 acc -----------
template<int KSTEPS, int MT, int NT8>
__device__ __forceinline__ void gemm(uint32_t smb, int warp, int lane, float (*acc)[4]) {
#pragma unroll
    for (int i = 0; i < MT * NT8; i++) { acc[i][0] = 0.f; acc[i][1] = 0.f; acc[i][2] = 0.f; acc[i][3] = 0.f; }
    const int R0 = (MT == 2) ? (warp & 1) * 32 : (warp & 3) * 16;
    const int N0 = (MT == 2) ? (warp >> 1) * 32 : (warp >> 2) * 16;
    const int m = lane >> 3, r = lane & 7;
    const uint32_t aBase = smb + A_HI + (uint32_t)((R0 + r + (m & 1) * 8) * ASTR + (m >> 1) * 16);
    const uint32_t bBase = smb + B_HI + (uint32_t)((N0 + r + ((m >> 1) << 3)) * ASTR + (m & 1) * 16);
#pragma unroll
    for (int ks = 0; ks < KSTEPS; ks++) {
        uint32_t aH[MT][4], aL[MT][4];
#pragma unroll
        for (int mt = 0; mt < MT; mt++) {
            LDSM4(aH[mt], aBase + mt * 16 * ASTR + ks * 32);
            LDSM4(aL[mt], aBase + (A_LO - A_HI) + mt * 16 * ASTR + ks * 32);
        }
#pragma unroll
        for (int gb = 0; gb < NT8 / 2; gb++) {
            uint32_t bH[4], bL[4];
            LDSM4(bH, bBase + gb * 16 * ASTR + ks * 32);
            LDSM4(bL, bBase + (B_LO - B_HI) + gb * 16 * ASTR + ks * 32);
#pragma unroll
            for (int mt = 0; mt < MT; mt++) {
                float* c0 = acc[mt * NT8 + 2 * gb];
                float* c1 = acc[mt * NT8 + 2 * gb + 1];
                MMA816(c0, aH[mt], bH[0], bH[1]);
                MMA816(c1, aH[mt], bH[2], bH[3]);
                MMA816(c0, aH[mt], bL[0], bL[1]);
                MMA816(c1, aH[mt], bL[2], bL[3]);
                MMA816(c0, aL[mt], bH[0], bH[1]);
                MMA816(c1, aL[mt], bH[2], bH[3]);
            }
        }
    }
}

// register epilogue: relu + bf16 split straight from accumulators into A tile (MT=2/NT8=4)
__device__ __forceinline__ void writebackA(char* sm, int warp, int lane, float (*acc)[4]) {
    const int R0 = (warp & 1) * 32, N0 = (warp >> 1) * 32;
    const int g = lane >> 2, t = lane & 3;
#pragma unroll
    for (int mt = 0; mt < 2; mt++) {
        int ra = R0 + 16 * mt + g;
#pragma unroll
        for (int j = 0; j < 4; j++) {
            const float* a = acc[mt * 4 + j];
            int c = N0 + 8 * j + 2 * t;
            uint32_t hi, lo;
            split_pair(fmaxf(a[0], 0.f), fmaxf(a[1], 0.f), hi, lo);
            *(uint32_t*)(sm + A_HI + ra * ASTR + c * 2) = hi;
            *(uint32_t*)(sm + A_LO + ra * ASTR + c * 2) = lo;
            split_pair(fmaxf(a[2], 0.f), fmaxf(a[3], 0.f), hi, lo);
            *(uint32_t*)(sm + A_HI + (ra + 8) * ASTR + c * 2) = hi;
            *(uint32_t*)(sm + A_LO + (ra + 8) * ASTR + c * 2) = lo;
        }
    }
}

// ---------------- weight prep (layout unchanged): Bt n-major, k-contiguous, 272B stride --------
struct WPtrs { const float* w[18]; };
__device__ const short P_widx[30] = {4,5,7,8, 9,9,9,9, 10,10,10,10, 11,11,11,11,
                                     12,12,12,12, 13,13,13,13, 14,14,14,14, 15,16};
__device__ const int   P_soff[30] = {0,0,0,0, 0,12288,24576,36864, 0,16384,32768,49152,
                                     0,4096,8192,12288, 0,8192,16384,24576,
                                     0,16384,32768,49152, 0,4096,8192,12288, 0,0};
__device__ const short P_K[30] = {128,128,128,128, 96,96,96,96, 128,128,128,128, 128,128,128,128,
                                  64,64,64,64, 128,128,128,128, 128,128,128,128, 32,128};
__device__ const short P_N[30] = {128,32,128,32, 128,128,128,128, 128,128,128,128, 32,32,32,32,
                                  128,128,128,128, 128,128,128,128, 32,32,32,32, 128,128};
__device__ const int   P_dst[30] = {0,34816,43520,78336,
                                    87040,165376,243712,322048,
                                    121856,200192,278528,356864,
                                    156672,235008,313344,391680,
                                    400384,478720,557056,635392,
                                    435200,513536,591872,670208,
                                    470016,548352,626688,705024,
                                    713728,748544};

__global__ void __launch_bounds__(256) prep_kernel(WPtrs P) {
    int b = blockIdx.x, t = 0, start = 0;
    for (; t < 30; t++) { int nb = (int)P_K[t] * (int)P_N[t] / 256; if (b < start + nb) break; start += nb; }
    int e = (b - start) * 256 + threadIdx.x;
    int N = P_N[t];
    int k = e / N, n = e % N;
    float v = P.w[P_widx[t]][P_soff[t] + e];
    __nv_bfloat16 h = __float2bfloat16(v);
    __nv_bfloat16 l = __float2bfloat16(v - __bfloat162float(h));
    int off = P_dst[t] + n * ASTR + k * 2;
    *(unsigned short*)(g_whi + off) = __bfloat16_as_ushort(h);
    *(unsigned short*)(g_wlo + off) = __bfloat16_as_ushort(l);
}

// ---------------- fused MLP; MODE: 0=ENC_N 1=ENC_E 2=EDGE 3=NODE 4=DEC; 64 rows/block ----------
template<int MODE>
__global__ void __launch_bounds__(256) mlp_mma(const float* __restrict__ in,
                                               const int* __restrict__ gi,
                                               const float* __restrict__ wraw,
                                               float* __restrict__ out,
                                               int wd0, int wd1, int wd2) {
    extern __shared__ char sm[];
    const uint32_t smb = smem_u32(sm);
    const int tid = threadIdx.x;
    const int warp = tid >> 5, lane = tid & 31;
    const int b0 = blockIdx.x * 64;
    const int row = tid >> 2, seg = tid & 3;

    // prefetch first weight layer while building A
    loadB_async(smb, wd0, 128 * 17, tid);
    CP_COMMIT();

    // ---------- build A tile (64 x K) ----------
    if (MODE == 2) {
        int s_ = gi[(b0 + row) * 2 + 0];      // 4 threads/row redundant, L1-hot
        int r_ = gi[(b0 + row) * 2 + 1];
#pragma unroll
        for (int f = 0; f < 6; f++) {
            int k = seg * 24 + f * 4;
            const float* src = (k < 32) ? (g_edge + (size_t)(b0 + row) * 32 + k)
                             : (k < 64) ? (g_node + (size_t)s_ * 32 + (k - 32))
                                        : (g_node + (size_t)r_ * 32 + (k - 64));
            float4 v = *(const float4*)src;
            storeA4(sm, row, k, v.x, v.y, v.z, v.w);
        }
    } else if (MODE == 3) {
#pragma unroll
        for (int f = 0; f < 4; f++) {
            int k = seg * 16 + f * 4;
            if (k < 32) {
                float4 v = *(const float4*)(g_node + (size_t)(b0 + row) * 32 + k);
                storeA4(sm, row, k, v.x, v.y, v.z, v.w);
            } else {
                float* pa = g_agg + (size_t)(b0 + row) * 32 + (k - 32);
                float4 v = *(const float4*)pa;
                storeA4(sm, row, k, v.x, v.y, v.z, v.w);
                *(float4*)pa = make_float4(0.f, 0.f, 0.f, 0.f);   // consume-and-zero for next iter
            }
        }
    } else if (MODE == 4) {
        if (tid < 128) ((float*)(sm + S_W0))[tid] = wraw[tid];
        if (tid < 64)  ((float*)(sm + S_OUT))[tid] = 0.f;
#pragma unroll
        for (int f = 0; f < 2; f++) {
            int k = seg * 8 + f * 4;
            float4 v = *(const float4*)(g_node + (size_t)(b0 + row) * 32 + k);
            storeA4(sm, row, k, v.x, v.y, v.z, v.w);
        }
    } else {  // encoders: SIMT layer0 (3 -> 128) + relu
        for (int i = tid; i < 384; i += 256)
            ((float*)(sm + S_W0))[i] = wraw[i];
        __syncthreads();
        float x0 = in[(b0 + row) * 3 + 0];
        float x1 = in[(b0 + row) * 3 + 1];
        float x2 = in[(b0 + row) * 3 + 2];
        const float* W0 = (const float*)(sm + S_W0);
#pragma unroll
        for (int f = 0; f < 8; f++) {
            int c = seg * 32 + f * 4;
            float h0 = fmaxf(fmaf(x0, W0[c + 0], fmaf(x1, W0[128 + c + 0], x2 * W0[256 + c + 0])), 0.f);
            float h1 = fmaxf(fmaf(x0, W0[c + 1], fmaf(x1, W0[128 + c + 1], x2 * W0[256 + c + 1])), 0.f);
            float h2 = fmaxf(fmaf(x0, W0[c + 2], fmaf(x1, W0[128 + c + 2], x2 * W0[256 + c + 2])), 0.f);
            float h3 = fmaxf(fmaf(x0, W0[c + 3], fmaf(x1, W0[128 + c + 3], x2 * W0[256 + c + 3])), 0.f);
            storeA4(sm, row, c, h0, h1, h2, h3);
        }
    }

    float acc[8][4];
    const int g = lane >> 2, t = lane & 3;

    if (MODE == 2 || MODE == 3) {
        CP_WAIT0(); __syncthreads();
        if (MODE == 2) gemm<6, 2, 4>(smb, warp, lane, acc);
        else           gemm<4, 2, 4>(smb, warp, lane, acc);
        __syncthreads();
        loadB_async(smb, wd1, 128 * 17, tid); CP_COMMIT();
        writebackA(sm, warp, lane, acc);
        CP_WAIT0(); __syncthreads();
        gemm<8, 2, 4>(smb, warp, lane, acc);
        __syncthreads();
        loadB_async(smb, wd2, 32 * 17, tid); CP_COMMIT();
        writebackA(sm, warp, lane, acc);
        CP_WAIT0(); __syncthreads();
        gemm<8, 1, 2>(smb, warp, lane, acc);
        // register epilogue: residual (+ vector-RED scatter for edges)
        {
            const int R0 = (warp & 3) * 16, N0 = (warp >> 2) * 16;
            float* dst = (MODE == 2) ? g_edge : g_node;
#pragma unroll
            for (int half = 0; half < 2; half++) {
                int r_ = R0 + g + half * 8;
                int rcv = (MODE == 2) ? gi[(b0 + r_) * 2 + 1] : 0;
#pragma unroll
                for (int j = 0; j < 2; j++) {
                    int c = N0 + 8 * j + 2 * t;
                    float* pe = dst + (size_t)(b0 + r_) * 32 + c;
                    float2 o = *(float2*)pe;
                    float v0 = acc[j][half * 2 + 0] + o.x;
                    float v1 = acc[j][half * 2 + 1] + o.y;
                    *(float2*)pe = make_float2(v0, v1);
                    if (MODE == 2)
                        REDV2(g_agg + (size_t)rcv * 32 + c, v0, v1);
                }
            }
        }
    } else if (MODE == 0 || MODE == 1) {
        CP_WAIT0(); __syncthreads();
        gemm<8, 2, 4>(smb, warp, lane, acc);
        __syncthreads();
        loadB_async(smb, wd1, 32 * 17, tid); CP_COMMIT();
        writebackA(sm, warp, lane, acc);
        CP_WAIT0(); __syncthreads();
        gemm<8, 1, 2>(smb, warp, lane, acc);
        {
            const int R0 = (warp & 3) * 16, N0 = (warp >> 2) * 16;
            float* dst = (MODE == 0) ? g_node : g_edge;
#pragma unroll
            for (int half = 0; half < 2; half++) {
                int r_ = R0 + g + half * 8;
#pragma unroll
                for (int j = 0; j < 2; j++) {
                    int c = N0 + 8 * j + 2 * t;
                    *(float2*)(dst + (size_t)(b0 + r_) * 32 + c) =
                        make_float2(acc[j][half * 2 + 0], acc[j][half * 2 + 1]);
                    if (MODE == 0)   // pre-zero agg rows for iteration 0's edge scatter
                        *(float2*)(g_agg + (size_t)(b0 + r_) * 32 + c) = make_float2(0.f, 0.f);
                }
            }
        }
    } else {  // DEC
        CP_WAIT0(); __syncthreads();
        gemm<2, 2, 4>(smb, warp, lane, acc);
        __syncthreads();
        loadB_async(smb, wd1, 128 * 17, tid); CP_COMMIT();
        writebackA(sm, warp, lane, acc);
        CP_WAIT0(); __syncthreads();
        gemm<8, 2, 4>(smb, warp, lane, acc);
        __syncthreads();    // S_OUT zero-init (done in build) visible; also A reads done
        {
            const int R0 = (warp & 1) * 32, N0 = (warp >> 1) * 32;
            const float* W2 = (const float*)(sm + S_W0);
            float* sout = (float*)(sm + S_OUT);
#pragma unroll
            for (int mt = 0; mt < 2; mt++) {
                float pa = 0.f, pb = 0.f;
#pragma unroll
                for (int j = 0; j < 4; j++) {
                    int c = N0 + 8 * j + 2 * t;
                    const float* a = acc[mt * 4 + j];
                    pa = fmaf(fmaxf(a[0], 0.f), W2[c], pa);
                    pa = fmaf(fmaxf(a[1], 0.f), W2[c + 1], pa);
                    pb = fmaf(fmaxf(a[2], 0.f), W2[c], pb);
                    pb = fmaf(fmaxf(a[3], 0.f), W2[c + 1], pb);
                }
                atomicAdd(&sout[R0 + 16 * mt + g], pa);
                atomicAdd(&sout[R0 + 16 * mt + g + 8], pb);
            }
            __syncthreads();
            if (tid < 64) out[b0 + tid] = sout[tid];
        }
    }
}

// ---------------- launch ----------------
extern "C" void kernel_launch(void* const* d_in, const int* in_sizes, int n_in,
                              void* d_out, int out_size) {
    WPtrs P;
    for (int i = 0; i < 18; i++) P.w[i] = (const float*)d_in[i];
    const float* input_node = (const float*)d_in[0];
    const float* input_edge = (const float*)d_in[1];
    const int*   gi         = (const int*)d_in[2];
    float* out = (float*)d_out;

    cudaFuncSetAttribute(mlp_mma<0>, cudaFuncAttributeMaxDynamicSharedMemorySize, SM_DYN);
    cudaFuncSetAttribute(mlp_mma<1>, cudaFuncAttributeMaxDynamicSharedMemorySize, SM_DYN);
    cudaFuncSetAttribute(mlp_mma<2>, cudaFuncAttributeMaxDynamicSharedMemorySize, SM_DYN);
    cudaFuncSetAttribute(mlp_mma<3>, cudaFuncAttributeMaxDynamicSharedMemorySize, SM_DYN);
    cudaFuncSetAttribute(mlp_mma<4>, cudaFuncAttributeMaxDynamicSharedMemorySize, SM_DYN);

    prep_kernel<<<1200, 256>>>(P);

    mlp_mma<0><<<NN / 64, 256, SM_DYN>>>(input_node, nullptr, (const float*)d_in[3], nullptr,
                                         0, 34816, 0);
    mlp_mma<1><<<NE / 64, 256, SM_DYN>>>(input_edge, nullptr, (const float*)d_in[6], nullptr,
                                         43520, 78336, 0);

    for (int it = 0; it < 4; it++) {
        mlp_mma<2><<<NE / 64, 256, SM_DYN>>>(nullptr, gi, nullptr, nullptr,
                                             87040 + it * 78336,
                                             121856 + it * 78336,
                                             156672 + it * 78336);
        mlp_mma<3><<<NN / 64, 256, SM_DYN>>>(nullptr, nullptr, nullptr, nullptr,
                                             400384 + it * 78336,
                                             435200 + it * 78336,
                                             470016 + it * 78336);
    }
    mlp_mma<4><<<NN / 64, 256, SM_DYN>>>(nullptr, nullptr, (const float*)d_in[17], out,
                                         713728, 748544, 0);
}